// round 14
// baseline (speedup 1.0000x reference)
#include <cuda_runtime.h>
#include <cuda_fp16.h>
#include <math.h>
#include <stdint.h>

#define BATCH   2
#define CIN     512
#define NSEQ    2048
#define HEADS   16
#define DHEAD   64
#define HDIM    1024           // HEADS*DHEAD
#define O3      3072           // 3*HDIM
#define ATT_SCALE 8.0f

// Scratch (device globals: allocation-free scratch per harness rules)
__device__ float g_qkv[BATCH * O3 * NSEQ];     // [b][o][n], q/k normalized in place
__device__ float g_ao [BATCH * HDIM * NSEQ];   // attention output [b][c][n]

// ===========================================================================
// helpers (baseline PTX, valid on plain sm_103 — no 'a' features)
// ===========================================================================
__device__ __forceinline__ uint32_t pack_h2(float lo, float hi) {
    __half2 h = __floats2half2_rn(lo, hi);
    return *(uint32_t*)&h;
}

// fp16: D(16x8,f32) += A(16x16 row,f16) * B(16x8 col,f16)
// a = [{A(g,2t),A(g,2t+1)}, {A(g+8,2t),A(g+8,2t+1)},
//      {A(g,2t+8),A(g,2t+9)}, {A(g+8,2t+8),A(g+8,2t+9)}]
// b = [{B(2t,g),B(2t+1,g)}, {B(2t+8,g),B(2t+9,g)}]     g=lane>>2, t=lane&3
// d = [D(g,2t), D(g,2t+1), D(g+8,2t), D(g+8,2t+1)]
__device__ __forceinline__ void mma_f16(float* d, const uint32_t* a,
                                        uint32_t b0, uint32_t b1) {
    asm volatile(
        "mma.sync.aligned.m16n8k16.row.col.f32.f16.f16.f32 "
        "{%0,%1,%2,%3}, {%4,%5,%6,%7}, {%8,%9}, {%0,%1,%2,%3};"
        : "+f"(d[0]), "+f"(d[1]), "+f"(d[2]), "+f"(d[3])
        : "r"(a[0]), "r"(a[1]), "r"(a[2]), "r"(a[3]), "r"(b0), "r"(b1));
}

// ===========================================================================
// fp16 mma.sync GEMM v2: Out[b][m][n] = sum_k W[m][k] * X[b][k][n] (+ bias)
// CTA tile 128m x 128n, 8 warps as 4(m) x 2(n), warp tile 32m x 64n.
// K-chunk 64 (4 k16 steps), DOUBLE-BUFFERED smem (2 x 32KB), register
// prefetch of chunk c+1 during compute of chunk c, ONE sync per chunk.
// Fragment layouts identical to the proven round-13 kernel (kc 0..3):
//   A frag f = mt*4+kc : 128 uint32 (LDS.128 per warp-operand)
//   B frag f = nt*4+kc :  64 uint32 (LDS.64 per warp-operand)
// ===========================================================================
#define GT_SMEM_BYTES (16384 * 4)   // 64KB: [Af0 4096][Bf0 4096][Af1][Bf1]

__global__ __launch_bounds__(256)
void f16_gemm_kernel(const float* __restrict__ W,   // [M][K]
                     const float* __restrict__ X,   // [b][K][N]
                     float* __restrict__ Out,       // [b][M][N]
                     const float* __restrict__ bias,
                     int M, int K, int N)
{
    extern __shared__ uint32_t gs[];

    const int tid  = threadIdx.x;
    const int wid  = tid >> 5;
    const int lane = tid & 31;
    const int g = lane >> 2;
    const int t = lane & 3;
    const int wm = wid >> 1;
    const int wn = wid & 1;

    const int n0 = blockIdx.x * 128;
    const int m0 = blockIdx.y * 128;
    const int b  = blockIdx.z;

    const float* Ab = W + (size_t)m0 * K;
    const float* Xb = X + (size_t)b * K * N + n0;

    float d[2][8][4];
    #pragma unroll
    for (int a = 0; a < 2; a++)
        #pragma unroll
        for (int j = 0; j < 8; j++)
            #pragma unroll
            for (int r = 0; r < 4; r++) d[a][j][r] = 0.0f;

    // prefetch registers for one K-64 chunk (per warp: A mt=wid kc0..3;
    // B nt=2w,2w+1 kc0..3)
    uint4 av[4];
    uint2 bv[8];

    // ---- load chunk k0 into registers (pack to fp16 immediately)
    auto load_chunk = [&](int k0) {
        #pragma unroll
        for (int kc = 0; kc < 4; kc++) {
            const float* ap = Ab + (size_t)(wid * 16 + g) * K + (k0 + kc * 16 + 2 * t);
            float2 q0 = *(const float2*)ap;
            float2 q1 = *(const float2*)(ap + (size_t)8 * K);
            float2 q2 = *(const float2*)(ap + 8);
            float2 q3 = *(const float2*)(ap + (size_t)8 * K + 8);
            av[kc].x = pack_h2(q0.x, q0.y);
            av[kc].y = pack_h2(q1.x, q1.y);
            av[kc].z = pack_h2(q2.x, q2.y);
            av[kc].w = pack_h2(q3.x, q3.y);
        }
        #pragma unroll
        for (int i = 0; i < 8; i++) {
            const int nt = wid * 2 + (i >> 2);
            const int kc = i & 3;
            const float* bp = Xb + (size_t)(k0 + kc * 16 + 2 * t) * N + (nt * 8 + g);
            bv[i].x = pack_h2(bp[0], bp[N]);
            bv[i].y = pack_h2(bp[(size_t)8 * N], bp[(size_t)9 * N]);
        }
    };
    // ---- publish registers into buffer `buf`
    auto store_chunk = [&](int buf) {
        uint32_t* Af = gs + buf * 8192;
        uint32_t* Bf = Af + 4096;
        #pragma unroll
        for (int kc = 0; kc < 4; kc++)
            *(uint4*)(Af + (wid * 4 + kc) * 128 + lane * 4) = av[kc];
        #pragma unroll
        for (int i = 0; i < 8; i++) {
            const int nt = wid * 2 + (i >> 2);
            const int kc = i & 3;
            *(uint2*)(Bf + (nt * 4 + kc) * 64 + lane * 2) = bv[i];
        }
    };

    load_chunk(0);
    store_chunk(0);
    __syncthreads();

    const int nch = K >> 6;
    for (int c = 0; c < nch; c++) {
        // ---- issue next chunk's LDGs early (overlap with MMAs below)
        if (c + 1 < nch) load_chunk((c + 1) << 6);

        // ---- compute chunk c from buffer c&1
        const uint32_t* Af = gs + (c & 1) * 8192;
        const uint32_t* Bf = Af + 4096;
        #pragma unroll
        for (int kc = 0; kc < 4; kc++) {
            uint4 a0 = *(const uint4*)(Af + ((wm * 2    ) * 4 + kc) * 128 + lane * 4);
            uint4 a1 = *(const uint4*)(Af + ((wm * 2 + 1) * 4 + kc) * 128 + lane * 4);
            #pragma unroll
            for (int j = 0; j < 8; j++) {
                uint2 bb = *(const uint2*)(Bf + ((wn * 8 + j) * 4 + kc) * 64 + lane * 2);
                mma_f16(d[0][j], (const uint32_t*)&a0, bb.x, bb.y);
                mma_f16(d[1][j], (const uint32_t*)&a1, bb.x, bb.y);
            }
        }

        // ---- publish chunk c+1, single sync
        if (c + 1 < nch) {
            store_chunk((c + 1) & 1);
            __syncthreads();
        }
    }

    // ---- epilogue: coalesced float2 stores (+bias)
    float* Ob = Out + (size_t)b * M * N;
    #pragma unroll
    for (int a = 0; a < 2; a++) {
        const int row = m0 + wm * 32 + a * 16 + g;
        const float b1 = bias ? bias[row]     : 0.0f;
        const float b2 = bias ? bias[row + 8] : 0.0f;
        #pragma unroll
        for (int j = 0; j < 8; j++) {
            const int col = n0 + wn * 64 + j * 8 + t * 2;
            float2 v0; v0.x = d[a][j][0] + b1; v0.y = d[a][j][1] + b1;
            float2 v1; v1.x = d[a][j][2] + b2; v1.y = d[a][j][3] + b2;
            *(float2*)(Ob + (size_t)row * N + col)       = v0;
            *(float2*)(Ob + (size_t)(row + 8) * N + col) = v1;
        }
    }
}

// ---------------------------------------------------------------------------
// L2 normalization of q,k over head-dim (in place in g_qkv), applying scales.
// ---------------------------------------------------------------------------
__global__ __launch_bounds__(256)
void l2norm_kernel(float* __restrict__ qkv,
                   const float* __restrict__ qs,
                   const float* __restrict__ ks)
{
    const int n  = blockIdx.x * 256 + threadIdx.x;
    const int h  = blockIdx.y;
    const int bw = blockIdx.z;
    const int b  = bw >> 1;
    const int w  = bw & 1;
    const float* sc = w ? ks : qs;

    float* base = qkv + ((size_t)b * O3 + (size_t)w * HDIM + (size_t)h * DHEAD) * NSEQ + n;

    float ss = 0.0f;
    #pragma unroll
    for (int d = 0; d < DHEAD; d++) {
        float v = base[(size_t)d * NSEQ];
        ss += v * v;
    }
    float inv = 1.0f / fmaxf(sqrtf(ss), 1e-12f);
    #pragma unroll
    for (int d = 0; d < DHEAD; d++) {
        base[(size_t)d * NSEQ] = base[(size_t)d * NSEQ] * inv * sc[d];
    }
}

// ===========================================================================
// Flash attention v5 (round-12 proven, unchanged): fp16 m16n8k16,
// fixed-shift softmax P' = exp(s+1), register-direct P.
// ===========================================================================
#define ATT_SMEM_BYTES (64 * 132 * 4)

__global__ __launch_bounds__(256, 2)
void attn_f16_kernel(const float* __restrict__ qkv, float* __restrict__ ao)
{
    extern __shared__ char smc[];
    uint2* Kf = (uint2*)smc;          // 32 frags * 32 lanes (8KB)
    uint2* Vf = Kf + 1024;            // 8KB
    float* Ts = (float*)smc;          // epilogue reuse (64 x 132)

    const int tid  = threadIdx.x;
    const int wid  = tid >> 5;
    const int lane = tid & 31;
    const int g = lane >> 2;
    const int t = lane & 3;
    const int r0 = wid * 16;

    const int i0 = blockIdx.x * 128;
    const int h  = blockIdx.y;
    const int b  = blockIdx.z;

    const float* qb = qkv + ((size_t)b * O3 + (size_t)h * DHEAD) * NSEQ;
    const float* kb = qb + (size_t)HDIM * NSEQ;
    const float* vb = qb + (size_t)(2 * HDIM) * NSEQ;

    // ---- Q A-fragments (fp16), live whole kernel
    uint32_t qf[4][4];
    {
        const int col = i0 + r0 + g;
        #pragma unroll
        for (int kc = 0; kc < 4; kc++) {
            const float* q0 = qb + (size_t)(kc * 16 + 2 * t) * NSEQ + col;
            const float* q1 = q0 + NSEQ;
            qf[kc][0] = pack_h2(q0[0] * ATT_SCALE, q1[0] * ATT_SCALE);
            qf[kc][1] = pack_h2(q0[8] * ATT_SCALE, q1[8] * ATT_SCALE);
            qf[kc][2] = pack_h2(q0[(size_t)8 * NSEQ] * ATT_SCALE,
                                q1[(size_t)8 * NSEQ] * ATT_SCALE);
            qf[kc][3] = pack_h2(q0[(size_t)8 * NSEQ + 8] * ATT_SCALE,
                                q1[(size_t)8 * NSEQ + 8] * ATT_SCALE);
        }
    }

    // ---- preload K tile 0 (warp w stages frags nt=w, kc=0..3)
    float kreg[4][4];
    #pragma unroll
    for (int kc = 0; kc < 4; kc++) {
        const float* kp = kb + (size_t)(kc * 16 + 2 * t) * NSEQ + wid * 8 + g;
        kreg[kc][0] = kp[0];
        kreg[kc][1] = kp[NSEQ];
        kreg[kc][2] = kp[(size_t)8 * NSEQ];
        kreg[kc][3] = kp[(size_t)9 * NSEQ];
    }

    float lp0 = 0.0f, lp1 = 0.0f;
    float o[8][4];
    #pragma unroll
    for (int dt = 0; dt < 8; dt++)
        #pragma unroll
        for (int r = 0; r < 4; r++) o[dt][r] = 0.0f;

    for (int j0 = 0; j0 < NSEQ; j0 += 64) {
        #pragma unroll
        for (int kc = 0; kc < 4; kc++) {
            uint2 u;
            u.x = pack_h2(kreg[kc][0], kreg[kc][1]);
            u.y = pack_h2(kreg[kc][2], kreg[kc][3]);
            Kf[(wid * 4 + kc) * 32 + lane] = u;
        }
        __syncthreads();

        float2 vreg[4][2];
        #pragma unroll
        for (int kc = 0; kc < 4; kc++) {
            const float* vp = vb + (size_t)(wid * 8 + g) * NSEQ + j0 + kc * 16 + 2 * t;
            vreg[kc][0] = *(const float2*)vp;
            vreg[kc][1] = *(const float2*)(vp + 8);
        }

        float s[8][4];
        #pragma unroll
        for (int nt = 0; nt < 8; nt++)
            #pragma unroll
            for (int r = 0; r < 4; r++) s[nt][r] = 0.0f;

        #pragma unroll
        for (int kc = 0; kc < 4; kc++)
            #pragma unroll
            for (int nt = 0; nt < 8; nt++) {
                uint2 kb2 = Kf[(nt * 4 + kc) * 32 + lane];
                mma_f16(s[nt], qf[kc], kb2.x, kb2.y);
            }

        #pragma unroll
        for (int nt = 0; nt < 8; nt++) {
            s[nt][0] = __expf(s[nt][0] + 1.0f);
            s[nt][1] = __expf(s[nt][1] + 1.0f);
            s[nt][2] = __expf(s[nt][2] + 1.0f);
            s[nt][3] = __expf(s[nt][3] + 1.0f);
            lp0 += s[nt][0] + s[nt][1];
            lp1 += s[nt][2] + s[nt][3];
        }
        uint32_t pa[4][4];
        #pragma unroll
        for (int kc = 0; kc < 4; kc++) {
            pa[kc][0] = pack_h2(s[2 * kc][0],     s[2 * kc][1]);
            pa[kc][1] = pack_h2(s[2 * kc][2],     s[2 * kc][3]);
            pa[kc][2] = pack_h2(s[2 * kc + 1][0], s[2 * kc + 1][1]);
            pa[kc][3] = pack_h2(s[2 * kc + 1][2], s[2 * kc + 1][3]);
        }

        #pragma unroll
        for (int kc = 0; kc < 4; kc++) {
            uint2 u;
            u.x = pack_h2(vreg[kc][0].x, vreg[kc][0].y);
            u.y = pack_h2(vreg[kc][1].x, vreg[kc][1].y);
            Vf[(wid * 4 + kc) * 32 + lane] = u;
        }
        __syncthreads();

        const int jn = (j0 + 64 < NSEQ) ? j0 + 64 : 0;
        #pragma unroll
        for (int kc = 0; kc < 4; kc++) {
            const float* kp = kb + (size_t)(kc * 16 + 2 * t) * NSEQ + jn + wid * 8 + g;
            kreg[kc][0] = kp[0];
            kreg[kc][1] = kp[NSEQ];
            kreg[kc][2] = kp[(size_t)8 * NSEQ];
            kreg[kc][3] = kp[(size_t)9 * NSEQ];
        }

        #pragma unroll
        for (int kc = 0; kc < 4; kc++)
            #pragma unroll
            for (int dt = 0; dt < 8; dt++) {
                uint2 vb2 = Vf[(dt * 4 + kc) * 32 + lane];
                mma_f16(o[dt], pa[kc], vb2.x, vb2.y);
            }
    }

    lp0 += __shfl_xor_sync(0xffffffffu, lp0, 1);
    lp0 += __shfl_xor_sync(0xffffffffu, lp0, 2);
    lp1 += __shfl_xor_sync(0xffffffffu, lp1, 1);
    lp1 += __shfl_xor_sync(0xffffffffu, lp1, 2);
    const float inv0 = 1.0f / lp0;
    const float inv1 = 1.0f / lp1;

    __syncthreads();

    #pragma unroll
    for (int dt = 0; dt < 8; dt++) {
        Ts[(dt * 8 + 2 * t)     * 132 + r0 + g]     = o[dt][0] * inv0;
        Ts[(dt * 8 + 2 * t + 1) * 132 + r0 + g]     = o[dt][1] * inv0;
        Ts[(dt * 8 + 2 * t)     * 132 + r0 + g + 8] = o[dt][2] * inv1;
        Ts[(dt * 8 + 2 * t + 1) * 132 + r0 + g + 8] = o[dt][3] * inv1;
    }
    __syncthreads();

    float* aob = ao + ((size_t)b * HDIM + (size_t)h * DHEAD) * NSEQ;
    for (int e = tid; e < 64 * 128; e += 256) {
        int d = e >> 7, i = e & 127;
        aob[(size_t)d * NSEQ + i0 + i] = Ts[d * 132 + i];
    }
}

// ---------------------------------------------------------------------------
extern "C" void kernel_launch(void* const* d_in, const int* in_sizes, int n_in,
                              void* d_out, int out_size)
{
    const float* x       = (const float*)d_in[0];
    const float* Wqkv    = (const float*)d_in[1];
    const float* q_scale = (const float*)d_in[2];
    const float* k_scale = (const float*)d_in[3];
    const float* Wout    = (const float*)d_in[4];
    const float* bout    = (const float*)d_in[5];
    float*       out     = (float*)d_out;

    float *qkv = nullptr, *ao = nullptr;
    cudaGetSymbolAddress((void**)&qkv, g_qkv);
    cudaGetSymbolAddress((void**)&ao,  g_ao);

    cudaFuncSetAttribute(f16_gemm_kernel,
                         cudaFuncAttributeMaxDynamicSharedMemorySize, GT_SMEM_BYTES);
    cudaFuncSetAttribute(attn_f16_kernel,
                         cudaFuncAttributeMaxDynamicSharedMemorySize, ATT_SMEM_BYTES);

    // 1) QKV projection (fp16, double-buffered K64): M=3072, K=512, N=2048
    f16_gemm_kernel<<<dim3(NSEQ / 128, O3 / 128, BATCH), 256, GT_SMEM_BYTES>>>(
        Wqkv, x, qkv, nullptr, O3, CIN, NSEQ);

    // 2) l2-normalize q,k in place (+ learned per-dim scales)
    l2norm_kernel<<<dim3(NSEQ / 256, HEADS, BATCH * 2), 256>>>(
        qkv, q_scale, k_scale);

    // 3) flash attention (fp16 mma.sync, register-direct P)
    attn_f16_kernel<<<dim3(NSEQ / 128, HEADS, BATCH), 256, ATT_SMEM_BYTES>>>(qkv, ao);

    // 4) output projection (fp16, double-buffered K64) + bias: M=512, K=1024, N=2048
    f16_gemm_kernel<<<dim3(NSEQ / 128, CIN / 128, BATCH), 256, GT_SMEM_BYTES>>>(
        Wout, ao, out, bout, CIN, HDIM, NSEQ);
}

// round 15
// speedup vs baseline: 1.1939x; 1.1939x over previous
#include <cuda_runtime.h>
#include <cuda_fp16.h>
#include <math.h>
#include <stdint.h>

#define BATCH   2
#define CIN     512
#define NSEQ    2048
#define HEADS   16
#define DHEAD   64
#define HDIM    1024           // HEADS*DHEAD
#define O3      3072           // 3*HDIM
#define ATT_SCALE 8.0f

// Scratch (device globals: allocation-free scratch per harness rules)
__device__ float    g_qkv[BATCH * O3 * NSEQ];          // fp32 qkv (l2norm in place)
__device__ uint32_t g_wqkv16[O3 * CIN / 2];            // Wqkv A-frag fp16 image
__device__ uint32_t g_wout16[CIN * HDIM / 2];          // Wout A-frag fp16 image
__device__ uint32_t g_x16 [BATCH * CIN * NSEQ / 2];    // x B-frag fp16 image
__device__ uint32_t g_ao16[BATCH * HDIM * NSEQ / 2];   // attn-out B-frag fp16 image

// ===========================================================================
// helpers (baseline PTX, valid on plain sm_103 — no 'a' features)
// ===========================================================================
__device__ __forceinline__ uint32_t pack_h2(float lo, float hi) {
    __half2 h = __floats2half2_rn(lo, hi);
    return *(uint32_t*)&h;
}

// fp16: D(16x8,f32) += A(16x16 row,f16) * B(16x8 col,f16)
// a = [{A(g,2t),A(g,2t+1)}, {A(g+8,2t),A(g+8,2t+1)},
//      {A(g,2t+8),A(g,2t+9)}, {A(g+8,2t+8),A(g+8,2t+9)}]
// b = [{B(2t,g),B(2t+1,g)}, {B(2t+8,g),B(2t+9,g)}]     g=lane>>2, t=lane&3
// d = [D(g,2t), D(g,2t+1), D(g+8,2t), D(g+8,2t+1)]
__device__ __forceinline__ void mma_f16(float* d, const uint32_t* a,
                                        uint32_t b0, uint32_t b1) {
    asm volatile(
        "mma.sync.aligned.m16n8k16.row.col.f32.f16.f16.f32 "
        "{%0,%1,%2,%3}, {%4,%5,%6,%7}, {%8,%9}, {%0,%1,%2,%3};"
        : "+f"(d[0]), "+f"(d[1]), "+f"(d[2]), "+f"(d[3])
        : "r"(a[0]), "r"(a[1]), "r"(a[2]), "r"(a[3]), "r"(b0), "r"(b1));
}

// ===========================================================================
// Pre-pass: W[M][K] fp32 -> A-fragment fp16 image.
// frag f = mt*(K/16)+kc : 128 uint32; lane word u4 at f*128 + lane*4.
// ===========================================================================
__global__ __launch_bounds__(256)
void pack_a_kernel(const float* __restrict__ W, uint32_t* __restrict__ out,
                   int M, int K)
{
    const int idx = blockIdx.x * 256 + threadIdx.x;
    const int total = (M >> 4) * (K >> 4) * 32;
    if (idx >= total) return;
    const int lane = idx & 31;
    const int f    = idx >> 5;
    const int Kc   = K >> 4;
    const int kc   = f % Kc;
    const int mt   = f / Kc;
    const int g = lane >> 2, t = lane & 3;

    const float* ap = W + (size_t)(mt * 16 + g) * K + kc * 16 + 2 * t;
    uint4 u;
    u.x = pack_h2(ap[0],               ap[1]);
    u.y = pack_h2(ap[(size_t)8 * K],   ap[(size_t)8 * K + 1]);
    u.z = pack_h2(ap[8],               ap[9]);
    u.w = pack_h2(ap[(size_t)8 * K + 8], ap[(size_t)8 * K + 9]);
    *(uint4*)(out + (size_t)f * 128 + lane * 4) = u;
}

// ===========================================================================
// Pre-pass: X[b][K][N] fp32 -> B-fragment fp16 image.
// frag (b, ntG, kc): 64 uint32 at ((b*(N/8)+ntG)*(K/16)+kc)*64 + lane*2.
// word: x = {X(16kc+2t, 8ntG+g), X(+1,..)}, y = {X(+8,..), X(+9,..)}
// ===========================================================================
__global__ __launch_bounds__(256)
void pack_b_kernel(const float* __restrict__ X, uint32_t* __restrict__ out,
                   int K, int N)
{
    const int idx = blockIdx.x * 256 + threadIdx.x;
    const int total = (N >> 3) * (K >> 4) * 32;
    if (idx >= total) return;
    const int b = blockIdx.y;
    const int lane = idx & 31;
    const int f    = idx >> 5;
    const int Kc   = K >> 4;
    const int kc   = f % Kc;
    const int ntG  = f / Kc;
    const int g = lane >> 2, t = lane & 3;

    const float* bp = X + (size_t)b * K * N + (size_t)(kc * 16 + 2 * t) * N + ntG * 8 + g;
    uint2 u;
    u.x = pack_h2(bp[0],               bp[N]);
    u.y = pack_h2(bp[(size_t)8 * N],   bp[(size_t)9 * N]);
    *(uint2*)(out + ((size_t)(b * (N >> 3) + ntG) * Kc + kc) * 64 + lane * 2) = u;
}

// ===========================================================================
// fp16 mma.sync GEMM v3: pre-packed fragment images, K-chunk 64,
// double-buffered smem, register prefetch, one sync per chunk.
// Staging per thread per chunk: 4 LDG.128 (A) + 8 LDG.64 (B), zero cvts.
// ===========================================================================
#define GT_SMEM_BYTES (16384 * 4)   // 64KB: [Af0 4096][Bf0 4096][Af1][Bf1]

__global__ __launch_bounds__(256)
void f16_gemm_kernel(const uint32_t* __restrict__ Aimg,  // A-frag image
                     const uint32_t* __restrict__ Bimg,  // B-frag image
                     float* __restrict__ Out,            // [b][M][N]
                     const float* __restrict__ bias,
                     int M, int K, int N)
{
    extern __shared__ uint32_t gs[];

    const int tid  = threadIdx.x;
    const int wid  = tid >> 5;
    const int lane = tid & 31;
    const int g = lane >> 2;
    const int t = lane & 3;
    const int wm = wid >> 1;
    const int wn = wid & 1;

    const int n0 = blockIdx.x * 128;
    const int m0 = blockIdx.y * 128;
    const int b  = blockIdx.z;

    const int Kc = K >> 4;
    // per-warp image bases
    const uint32_t* Abase = Aimg + ((size_t)(m0 / 16 + wid) * Kc) * 128 + lane * 4;
    const size_t    bntBase = (size_t)(b * (N >> 3) + n0 / 8);

    float d[2][8][4];
    #pragma unroll
    for (int a = 0; a < 2; a++)
        #pragma unroll
        for (int j = 0; j < 8; j++)
            #pragma unroll
            for (int r = 0; r < 4; r++) d[a][j][r] = 0.0f;

    uint4 av[4];
    uint2 bv[8];

    auto load_chunk = [&](int kc0) {      // kc0 in 16-k units
        #pragma unroll
        for (int kc = 0; kc < 4; kc++)
            av[kc] = *(const uint4*)(Abase + (size_t)(kc0 + kc) * 128);
        #pragma unroll
        for (int i = 0; i < 8; i++) {
            const int ntL = wid * 2 + (i >> 2);
            const int kcL = i & 3;
            bv[i] = *(const uint2*)(Bimg + ((bntBase + ntL) * Kc + kc0 + kcL) * 64
                                    + lane * 2);
        }
    };
    auto store_chunk = [&](int buf) {
        uint32_t* Af = gs + buf * 8192;
        uint32_t* Bf = Af + 4096;
        #pragma unroll
        for (int kc = 0; kc < 4; kc++)
            *(uint4*)(Af + (wid * 4 + kc) * 128 + lane * 4) = av[kc];
        #pragma unroll
        for (int i = 0; i < 8; i++) {
            const int ntL = wid * 2 + (i >> 2);
            const int kcL = i & 3;
            *(uint2*)(Bf + (ntL * 4 + kcL) * 64 + lane * 2) = bv[i];
        }
    };

    load_chunk(0);
    store_chunk(0);
    __syncthreads();

    const int nch = K >> 6;
    for (int c = 0; c < nch; c++) {
        if (c + 1 < nch) load_chunk((c + 1) * 4);

        const uint32_t* Af = gs + (c & 1) * 8192;
        const uint32_t* Bf = Af + 4096;
        #pragma unroll
        for (int kc = 0; kc < 4; kc++) {
            uint4 a0 = *(const uint4*)(Af + ((wm * 2    ) * 4 + kc) * 128 + lane * 4);
            uint4 a1 = *(const uint4*)(Af + ((wm * 2 + 1) * 4 + kc) * 128 + lane * 4);
            #pragma unroll
            for (int j = 0; j < 8; j++) {
                uint2 bb = *(const uint2*)(Bf + ((wn * 8 + j) * 4 + kc) * 64 + lane * 2);
                mma_f16(d[0][j], (const uint32_t*)&a0, bb.x, bb.y);
                mma_f16(d[1][j], (const uint32_t*)&a1, bb.x, bb.y);
            }
        }

        if (c + 1 < nch) {
            store_chunk((c + 1) & 1);
            __syncthreads();
        }
    }

    float* Ob = Out + (size_t)b * M * N;
    #pragma unroll
    for (int a = 0; a < 2; a++) {
        const int row = m0 + wm * 32 + a * 16 + g;
        const float b1 = bias ? bias[row]     : 0.0f;
        const float b2 = bias ? bias[row + 8] : 0.0f;
        #pragma unroll
        for (int j = 0; j < 8; j++) {
            const int col = n0 + wn * 64 + j * 8 + t * 2;
            float2 v0; v0.x = d[a][j][0] + b1; v0.y = d[a][j][1] + b1;
            float2 v1; v1.x = d[a][j][2] + b2; v1.y = d[a][j][3] + b2;
            *(float2*)(Ob + (size_t)row * N + col)       = v0;
            *(float2*)(Ob + (size_t)(row + 8) * N + col) = v1;
        }
    }
}

// ---------------------------------------------------------------------------
// L2 normalization of q,k over head-dim (in place in g_qkv), applying scales.
// ---------------------------------------------------------------------------
__global__ __launch_bounds__(256)
void l2norm_kernel(float* __restrict__ qkv,
                   const float* __restrict__ qs,
                   const float* __restrict__ ks)
{
    const int n  = blockIdx.x * 256 + threadIdx.x;
    const int h  = blockIdx.y;
    const int bw = blockIdx.z;
    const int b  = bw >> 1;
    const int w  = bw & 1;
    const float* sc = w ? ks : qs;

    float* base = qkv + ((size_t)b * O3 + (size_t)w * HDIM + (size_t)h * DHEAD) * NSEQ + n;

    float ss = 0.0f;
    #pragma unroll
    for (int d = 0; d < DHEAD; d++) {
        float v = base[(size_t)d * NSEQ];
        ss += v * v;
    }
    float inv = 1.0f / fmaxf(sqrtf(ss), 1e-12f);
    #pragma unroll
    for (int d = 0; d < DHEAD; d++) {
        base[(size_t)d * NSEQ] = base[(size_t)d * NSEQ] * inv * sc[d];
    }
}

// ===========================================================================
// Flash attention (round-12/13 proven core): fp16 m16n8k16, fixed-shift
// softmax P' = exp(s+1), register-direct P. Epilogue now writes the
// out-proj's B-fragment fp16 image directly (g_ao16).
// ===========================================================================
#define ATT_SMEM_BYTES (64 * 132 * 4)

__global__ __launch_bounds__(256, 2)
void attn_f16_kernel(const float* __restrict__ qkv, uint32_t* __restrict__ ao16)
{
    extern __shared__ char smc[];
    uint2* Kf = (uint2*)smc;          // 32 frags * 32 lanes (8KB)
    uint2* Vf = Kf + 1024;            // 8KB
    float* Ts = (float*)smc;          // epilogue reuse (64 x 132)

    const int tid  = threadIdx.x;
    const int wid  = tid >> 5;
    const int lane = tid & 31;
    const int g = lane >> 2;
    const int t = lane & 3;
    const int r0 = wid * 16;

    const int i0 = blockIdx.x * 128;
    const int h  = blockIdx.y;
    const int b  = blockIdx.z;

    const float* qb = qkv + ((size_t)b * O3 + (size_t)h * DHEAD) * NSEQ;
    const float* kb = qb + (size_t)HDIM * NSEQ;
    const float* vb = qb + (size_t)(2 * HDIM) * NSEQ;

    // ---- Q A-fragments (fp16), live whole kernel
    uint32_t qf[4][4];
    {
        const int col = i0 + r0 + g;
        #pragma unroll
        for (int kc = 0; kc < 4; kc++) {
            const float* q0 = qb + (size_t)(kc * 16 + 2 * t) * NSEQ + col;
            const float* q1 = q0 + NSEQ;
            qf[kc][0] = pack_h2(q0[0] * ATT_SCALE, q1[0] * ATT_SCALE);
            qf[kc][1] = pack_h2(q0[8] * ATT_SCALE, q1[8] * ATT_SCALE);
            qf[kc][2] = pack_h2(q0[(size_t)8 * NSEQ] * ATT_SCALE,
                                q1[(size_t)8 * NSEQ] * ATT_SCALE);
            qf[kc][3] = pack_h2(q0[(size_t)8 * NSEQ + 8] * ATT_SCALE,
                                q1[(size_t)8 * NSEQ + 8] * ATT_SCALE);
        }
    }

    // ---- preload K tile 0 (warp w stages frags nt=w, kc=0..3)
    float kreg[4][4];
    #pragma unroll
    for (int kc = 0; kc < 4; kc++) {
        const float* kp = kb + (size_t)(kc * 16 + 2 * t) * NSEQ + wid * 8 + g;
        kreg[kc][0] = kp[0];
        kreg[kc][1] = kp[NSEQ];
        kreg[kc][2] = kp[(size_t)8 * NSEQ];
        kreg[kc][3] = kp[(size_t)9 * NSEQ];
    }

    float lp0 = 0.0f, lp1 = 0.0f;
    float o[8][4];
    #pragma unroll
    for (int dt = 0; dt < 8; dt++)
        #pragma unroll
        for (int r = 0; r < 4; r++) o[dt][r] = 0.0f;

    for (int j0 = 0; j0 < NSEQ; j0 += 64) {
        #pragma unroll
        for (int kc = 0; kc < 4; kc++) {
            uint2 u;
            u.x = pack_h2(kreg[kc][0], kreg[kc][1]);
            u.y = pack_h2(kreg[kc][2], kreg[kc][3]);
            Kf[(wid * 4 + kc) * 32 + lane] = u;
        }
        __syncthreads();

        float2 vreg[4][2];
        #pragma unroll
        for (int kc = 0; kc < 4; kc++) {
            const float* vp = vb + (size_t)(wid * 8 + g) * NSEQ + j0 + kc * 16 + 2 * t;
            vreg[kc][0] = *(const float2*)vp;
            vreg[kc][1] = *(const float2*)(vp + 8);
        }

        float s[8][4];
        #pragma unroll
        for (int nt = 0; nt < 8; nt++)
            #pragma unroll
            for (int r = 0; r < 4; r++) s[nt][r] = 0.0f;

        #pragma unroll
        for (int kc = 0; kc < 4; kc++)
            #pragma unroll
            for (int nt = 0; nt < 8; nt++) {
                uint2 kb2 = Kf[(nt * 4 + kc) * 32 + lane];
                mma_f16(s[nt], qf[kc], kb2.x, kb2.y);
            }

        #pragma unroll
        for (int nt = 0; nt < 8; nt++) {
            s[nt][0] = __expf(s[nt][0] + 1.0f);
            s[nt][1] = __expf(s[nt][1] + 1.0f);
            s[nt][2] = __expf(s[nt][2] + 1.0f);
            s[nt][3] = __expf(s[nt][3] + 1.0f);
            lp0 += s[nt][0] + s[nt][1];
            lp1 += s[nt][2] + s[nt][3];
        }
        uint32_t pa[4][4];
        #pragma unroll
        for (int kc = 0; kc < 4; kc++) {
            pa[kc][0] = pack_h2(s[2 * kc][0],     s[2 * kc][1]);
            pa[kc][1] = pack_h2(s[2 * kc][2],     s[2 * kc][3]);
            pa[kc][2] = pack_h2(s[2 * kc + 1][0], s[2 * kc + 1][1]);
            pa[kc][3] = pack_h2(s[2 * kc + 1][2], s[2 * kc + 1][3]);
        }

        #pragma unroll
        for (int kc = 0; kc < 4; kc++) {
            uint2 u;
            u.x = pack_h2(vreg[kc][0].x, vreg[kc][0].y);
            u.y = pack_h2(vreg[kc][1].x, vreg[kc][1].y);
            Vf[(wid * 4 + kc) * 32 + lane] = u;
        }
        __syncthreads();

        const int jn = (j0 + 64 < NSEQ) ? j0 + 64 : 0;
        #pragma unroll
        for (int kc = 0; kc < 4; kc++) {
            const float* kp = kb + (size_t)(kc * 16 + 2 * t) * NSEQ + jn + wid * 8 + g;
            kreg[kc][0] = kp[0];
            kreg[kc][1] = kp[NSEQ];
            kreg[kc][2] = kp[(size_t)8 * NSEQ];
            kreg[kc][3] = kp[(size_t)9 * NSEQ];
        }

        #pragma unroll
        for (int kc = 0; kc < 4; kc++)
            #pragma unroll
            for (int dt = 0; dt < 8; dt++) {
                uint2 vb2 = Vf[(dt * 4 + kc) * 32 + lane];
                mma_f16(o[dt], pa[kc], vb2.x, vb2.y);
            }
    }

    lp0 += __shfl_xor_sync(0xffffffffu, lp0, 1);
    lp0 += __shfl_xor_sync(0xffffffffu, lp0, 2);
    lp1 += __shfl_xor_sync(0xffffffffu, lp1, 1);
    lp1 += __shfl_xor_sync(0xffffffffu, lp1, 2);
    const float inv0 = 1.0f / lp0;
    const float inv1 = 1.0f / lp1;

    __syncthreads();

    #pragma unroll
    for (int dt = 0; dt < 8; dt++) {
        Ts[(dt * 8 + 2 * t)     * 132 + r0 + g]     = o[dt][0] * inv0;
        Ts[(dt * 8 + 2 * t + 1) * 132 + r0 + g]     = o[dt][1] * inv0;
        Ts[(dt * 8 + 2 * t)     * 132 + r0 + g + 8] = o[dt][2] * inv1;
        Ts[(dt * 8 + 2 * t + 1) * 132 + r0 + g + 8] = o[dt][3] * inv1;
    }
    __syncthreads();

    // ---- write out-proj B-frag image: 2048 uint2 per CTA
    // word (ntL 0..15, kcL 0..3, lane): n = i0 + ntL*8 + g (token),
    // k = h*64 + kcL*16 + {2t,2t+1,2t+8,2t+9} (channel)
    for (int e = tid; e < 2048; e += 256) {
        const int ln  = e & 31;
        const int f   = e >> 5;          // ntL*4 + kcL
        const int kcL = f & 3;
        const int ntL = f >> 2;
        const int gg = ln >> 2, tt = ln & 3;
        const int i  = ntL * 8 + gg;
        const int d0 = kcL * 16 + 2 * tt;
        uint2 u;
        u.x = pack_h2(Ts[d0 * 132 + i],       Ts[(d0 + 1) * 132 + i]);
        u.y = pack_h2(Ts[(d0 + 8) * 132 + i], Ts[(d0 + 9) * 132 + i]);
        const size_t dst = ((size_t)(b * (NSEQ >> 3) + (i0 >> 3) + ntL) * (HDIM >> 4)
                            + (h * 4 + kcL)) * 64 + ln * 2;
        *(uint2*)(ao16 + dst) = u;
    }
}

// ---------------------------------------------------------------------------
extern "C" void kernel_launch(void* const* d_in, const int* in_sizes, int n_in,
                              void* d_out, int out_size)
{
    const float* x       = (const float*)d_in[0];
    const float* Wqkv    = (const float*)d_in[1];
    const float* q_scale = (const float*)d_in[2];
    const float* k_scale = (const float*)d_in[3];
    const float* Wout    = (const float*)d_in[4];
    const float* bout    = (const float*)d_in[5];
    float*       out     = (float*)d_out;

    float *qkv = nullptr;
    uint32_t *wq16 = nullptr, *wo16 = nullptr, *x16 = nullptr, *ao16 = nullptr;
    cudaGetSymbolAddress((void**)&qkv,  g_qkv);
    cudaGetSymbolAddress((void**)&wq16, g_wqkv16);
    cudaGetSymbolAddress((void**)&wo16, g_wout16);
    cudaGetSymbolAddress((void**)&x16,  g_x16);
    cudaGetSymbolAddress((void**)&ao16, g_ao16);

    cudaFuncSetAttribute(f16_gemm_kernel,
                         cudaFuncAttributeMaxDynamicSharedMemorySize, GT_SMEM_BYTES);
    cudaFuncSetAttribute(attn_f16_kernel,
                         cudaFuncAttributeMaxDynamicSharedMemorySize, ATT_SMEM_BYTES);

    // 0) pre-pack fp16 fragment images
    pack_a_kernel<<<(O3 / 16) * (CIN / 16) * 32 / 256, 256>>>(Wqkv, wq16, O3, CIN);
    pack_a_kernel<<<(CIN / 16) * (HDIM / 16) * 32 / 256, 256>>>(Wout, wo16, CIN, HDIM);
    {
        dim3 gb((NSEQ / 8) * (CIN / 16) * 32 / 256, BATCH);
        pack_b_kernel<<<gb, 256>>>(x, x16, CIN, NSEQ);
    }

    // 1) QKV projection (fp16, pre-packed, K64 double-buffered)
    f16_gemm_kernel<<<dim3(NSEQ / 128, O3 / 128, BATCH), 256, GT_SMEM_BYTES>>>(
        wq16, x16, qkv, nullptr, O3, CIN, NSEQ);

    // 2) l2-normalize q,k in place (+ learned per-dim scales)
    l2norm_kernel<<<dim3(NSEQ / 256, HEADS, BATCH * 2), 256>>>(
        qkv, q_scale, k_scale);

    // 3) flash attention; epilogue emits out-proj B-frag image
    attn_f16_kernel<<<dim3(NSEQ / 128, HEADS, BATCH), 256, ATT_SMEM_BYTES>>>(qkv, ao16);

    // 4) output projection (fp16, pre-packed) + bias
    f16_gemm_kernel<<<dim3(NSEQ / 128, CIN / 128, BATCH), 256, GT_SMEM_BYTES>>>(
        wo16, ao16, out, bout, CIN, HDIM, NSEQ);
}

// round 16
// speedup vs baseline: 1.5832x; 1.3260x over previous
#include <cuda_runtime.h>
#include <cuda_fp16.h>
#include <math.h>
#include <stdint.h>

#define BATCH   2
#define CIN     512
#define NSEQ    2048
#define HEADS   16
#define DHEAD   64
#define HDIM    1024           // HEADS*DHEAD
#define O3      3072           // 3*HDIM
#define ATT_SCALE 8.0f

// Scratch (device globals: allocation-free scratch per harness rules)
__device__ float    g_qkv[BATCH * O3 * NSEQ];          // fp32 qkv (q l2norm in place)
__device__ uint32_t g_wqkv16[O3 * CIN / 2];            // Wqkv A-frag fp16 image
__device__ uint32_t g_wout16[CIN * HDIM / 2];          // Wout A-frag fp16 image
__device__ uint32_t g_x16 [BATCH * CIN * NSEQ / 2];    // x B-frag fp16 image
__device__ uint32_t g_ao16[BATCH * HDIM * NSEQ / 2];   // attn-out B-frag fp16 image
__device__ uint32_t g_k16 [BATCH * HEADS * 256 * 4 * 64];  // K B-frag image (8MB)
__device__ uint32_t g_v16 [BATCH * HEADS * 8 * 128 * 64];  // V B-frag image (8MB)

// ===========================================================================
// helpers
// ===========================================================================
__device__ __forceinline__ uint32_t pack_h2(float lo, float hi) {
    __half2 h = __floats2half2_rn(lo, hi);
    return *(uint32_t*)&h;
}

__device__ __forceinline__ void mma_f16(float* d, const uint32_t* a,
                                        uint32_t b0, uint32_t b1) {
    asm volatile(
        "mma.sync.aligned.m16n8k16.row.col.f32.f16.f16.f32 "
        "{%0,%1,%2,%3}, {%4,%5,%6,%7}, {%8,%9}, {%0,%1,%2,%3};"
        : "+f"(d[0]), "+f"(d[1]), "+f"(d[2]), "+f"(d[3])
        : "r"(a[0]), "r"(a[1]), "r"(a[2]), "r"(a[3]), "r"(b0), "r"(b1));
}

// ===========================================================================
// Pre-pass: W[M][K] fp32 -> A-fragment fp16 image (proven round 15)
// ===========================================================================
__global__ __launch_bounds__(256)
void pack_a_kernel(const float* __restrict__ W, uint32_t* __restrict__ out,
                   int M, int K)
{
    const int idx = blockIdx.x * 256 + threadIdx.x;
    const int total = (M >> 4) * (K >> 4) * 32;
    if (idx >= total) return;
    const int lane = idx & 31;
    const int f    = idx >> 5;
    const int Kc   = K >> 4;
    const int kc   = f % Kc;
    const int mt   = f / Kc;
    const int g = lane >> 2, t = lane & 3;

    const float* ap = W + (size_t)(mt * 16 + g) * K + kc * 16 + 2 * t;
    uint4 u;
    u.x = pack_h2(ap[0],                 ap[1]);
    u.y = pack_h2(ap[(size_t)8 * K],     ap[(size_t)8 * K + 1]);
    u.z = pack_h2(ap[8],                 ap[9]);
    u.w = pack_h2(ap[(size_t)8 * K + 8], ap[(size_t)8 * K + 9]);
    *(uint4*)(out + (size_t)f * 128 + lane * 4) = u;
}

// ===========================================================================
// Pre-pass: X[b][K][N] fp32 -> B-fragment fp16 image (proven round 15)
// ===========================================================================
__global__ __launch_bounds__(256)
void pack_b_kernel(const float* __restrict__ X, uint32_t* __restrict__ out,
                   int K, int N)
{
    const int idx = blockIdx.x * 256 + threadIdx.x;
    const int total = (N >> 3) * (K >> 4) * 32;
    if (idx >= total) return;
    const int b = blockIdx.y;
    const int lane = idx & 31;
    const int f    = idx >> 5;
    const int Kc   = K >> 4;
    const int kc   = f % Kc;
    const int ntG  = f / Kc;
    const int g = lane >> 2, t = lane & 3;

    const float* bp = X + (size_t)b * K * N + (size_t)(kc * 16 + 2 * t) * N + ntG * 8 + g;
    uint2 u;
    u.x = pack_h2(bp[0],             bp[N]);
    u.y = pack_h2(bp[(size_t)8 * N], bp[(size_t)9 * N]);
    *(uint2*)(out + ((size_t)(b * (N >> 3) + ntG) * Kc + kc) * 64 + lane * 2) = u;
}

// ===========================================================================
// Pre-pass: V (from g_qkv) -> PV B-fragment fp16 image.
// frag (bh, dt 0..7, kcG 0..127): word x={V(j,d),V(j+1,d)}, y={V(j+8),V(j+9)}
// with d = 8dt+g, j = 16kcG+2t.  Identical pack values to round-15 attention.
// ===========================================================================
__global__ __launch_bounds__(256)
void pack_v_kernel(const float* __restrict__ qkv, uint32_t* __restrict__ out)
{
    const int idx = blockIdx.x * 256 + threadIdx.x;   // total = BH*8*128*32
    const int lane = idx & 31;
    int r = idx >> 5;
    const int kcG = r & 127; r >>= 7;
    const int dt  = r & 7;   r >>= 3;
    const int bh  = r;                                // b*HEADS + h
    const int b = bh >> 4, h = bh & 15;
    const int g = lane >> 2, t = lane & 3;

    const float* vb = qkv + ((size_t)b * O3 + 2 * HDIM + h * DHEAD) * NSEQ;
    const int d = dt * 8 + g;
    const int j = kcG * 16 + 2 * t;
    float2 p0 = *(const float2*)(vb + (size_t)d * NSEQ + j);
    float2 p1 = *(const float2*)(vb + (size_t)d * NSEQ + j + 8);
    uint2 u;
    u.x = pack_h2(p0.x, p0.y);
    u.y = pack_h2(p1.x, p1.y);
    *(uint2*)(out + ((size_t)(bh * 8 + dt) * 128 + kcG) * 64 + lane * 2) = u;
}

// ===========================================================================
// fp16 mma.sync GEMM v4: pre-packed images, K-chunk 32, double-buffered
// 2x16KB smem (2 CTAs/SM), register prefetch, one sync per chunk.
// ===========================================================================
#define GT_SMEM_BYTES (8192 * 4)   // 32KB: [Af0 2048][Bf0 2048][Af1][Bf1]

__global__ __launch_bounds__(256, 2)
void f16_gemm_kernel(const uint32_t* __restrict__ Aimg,
                     const uint32_t* __restrict__ Bimg,
                     float* __restrict__ Out,
                     const float* __restrict__ bias,
                     int M, int K, int N)
{
    extern __shared__ uint32_t gs[];

    const int tid  = threadIdx.x;
    const int wid  = tid >> 5;
    const int lane = tid & 31;
    const int g = lane >> 2;
    const int t = lane & 3;
    const int wm = wid >> 1;
    const int wn = wid & 1;

    const int n0 = blockIdx.x * 128;
    const int m0 = blockIdx.y * 128;
    const int b  = blockIdx.z;

    const int Kc = K >> 4;
    const uint32_t* Abase = Aimg + ((size_t)(m0 / 16 + wid) * Kc) * 128 + lane * 4;
    const size_t    bntBase = (size_t)(b * (N >> 3) + n0 / 8);

    float d[2][8][4];
    #pragma unroll
    for (int a = 0; a < 2; a++)
        #pragma unroll
        for (int j = 0; j < 8; j++)
            #pragma unroll
            for (int r = 0; r < 4; r++) d[a][j][r] = 0.0f;

    uint4 av[2];
    uint2 bv[4];

    auto load_chunk = [&](int kc0) {      // kc0 in 16-k units
        #pragma unroll
        for (int kc = 0; kc < 2; kc++)
            av[kc] = *(const uint4*)(Abase + (size_t)(kc0 + kc) * 128);
        #pragma unroll
        for (int i = 0; i < 4; i++) {
            const int ntL = wid * 2 + (i >> 1);
            const int kcL = i & 1;
            bv[i] = *(const uint2*)(Bimg + ((bntBase + ntL) * Kc + kc0 + kcL) * 64
                                    + lane * 2);
        }
    };
    auto store_chunk = [&](int buf) {
        uint32_t* Af = gs + buf * 4096;
        uint32_t* Bf = Af + 2048;
        #pragma unroll
        for (int kc = 0; kc < 2; kc++)
            *(uint4*)(Af + (wid * 2 + kc) * 128 + lane * 4) = av[kc];
        #pragma unroll
        for (int i = 0; i < 4; i++) {
            const int ntL = wid * 2 + (i >> 1);
            const int kcL = i & 1;
            *(uint2*)(Bf + (ntL * 2 + kcL) * 64 + lane * 2) = bv[i];
        }
    };

    load_chunk(0);
    store_chunk(0);
    __syncthreads();

    const int nch = K >> 5;
    for (int c = 0; c < nch; c++) {
        if (c + 1 < nch) load_chunk((c + 1) * 2);

        const uint32_t* Af = gs + (c & 1) * 4096;
        const uint32_t* Bf = Af + 2048;
        #pragma unroll
        for (int kc = 0; kc < 2; kc++) {
            uint4 a0 = *(const uint4*)(Af + ((wm * 2    ) * 2 + kc) * 128 + lane * 4);
            uint4 a1 = *(const uint4*)(Af + ((wm * 2 + 1) * 2 + kc) * 128 + lane * 4);
            #pragma unroll
            for (int j = 0; j < 8; j++) {
                uint2 bb = *(const uint2*)(Bf + ((wn * 8 + j) * 2 + kc) * 64 + lane * 2);
                mma_f16(d[0][j], (const uint32_t*)&a0, bb.x, bb.y);
                mma_f16(d[1][j], (const uint32_t*)&a1, bb.x, bb.y);
            }
        }

        if (c + 1 < nch) {
            store_chunk((c + 1) & 1);
            __syncthreads();
        }
    }

    float* Ob = Out + (size_t)b * M * N;
    #pragma unroll
    for (int a = 0; a < 2; a++) {
        const int row = m0 + wm * 32 + a * 16 + g;
        const float b1 = bias ? bias[row]     : 0.0f;
        const float b2 = bias ? bias[row + 8] : 0.0f;
        #pragma unroll
        for (int j = 0; j < 8; j++) {
            const int col = n0 + wn * 64 + j * 8 + t * 2;
            float2 v0; v0.x = d[a][j][0] + b1; v0.y = d[a][j][1] + b1;
            float2 v1; v1.x = d[a][j][2] + b2; v1.y = d[a][j][3] + b2;
            *(float2*)(Ob + (size_t)row * N + col)       = v0;
            *(float2*)(Ob + (size_t)(row + 8) * N + col) = v1;
        }
    }
}

// ---------------------------------------------------------------------------
// L2 normalization of q,k. q: writes back fp32 (attention Q prologue reads it).
// k: writes the K B-frag fp16 image DIRECTLY (fp32 writeback dropped).
// Pack values are bit-identical to round-15's in-attention packs.
// ---------------------------------------------------------------------------
__global__ __launch_bounds__(256)
void l2norm_kernel(float* __restrict__ qkv,
                   const float* __restrict__ qs,
                   const float* __restrict__ ks,
                   uint32_t* __restrict__ k16)
{
    const int n  = blockIdx.x * 256 + threadIdx.x;
    const int h  = blockIdx.y;
    const int bw = blockIdx.z;
    const int b  = bw >> 1;
    const int w  = bw & 1;
    const float* sc = w ? ks : qs;

    float* base = qkv + ((size_t)b * O3 + (size_t)w * HDIM + (size_t)h * DHEAD) * NSEQ + n;

    float ss = 0.0f;
    #pragma unroll
    for (int d = 0; d < DHEAD; d++) {
        float v = base[(size_t)d * NSEQ];
        ss += v * v;
    }
    float inv = 1.0f / fmaxf(sqrtf(ss), 1e-12f);

    if (w == 0) {
        #pragma unroll
        for (int d = 0; d < DHEAD; d++)
            base[(size_t)d * NSEQ] = base[(size_t)d * NSEQ] * inv * sc[d];
    } else {
        float kv[DHEAD];
        #pragma unroll
        for (int d = 0; d < DHEAD; d++)
            kv[d] = base[(size_t)d * NSEQ] * inv * sc[d];
        const int bh = b * HEADS + h;
        const size_t fragBase = ((size_t)bh * 256 + (n >> 3)) * 4;
        const int gl = (n & 7) * 4;
        #pragma unroll
        for (int kc = 0; kc < 4; kc++) {
            #pragma unroll
            for (int t = 0; t < 4; t++) {
                uint2 u;
                u.x = pack_h2(kv[kc * 16 + 2 * t],     kv[kc * 16 + 2 * t + 1]);
                u.y = pack_h2(kv[kc * 16 + 2 * t + 8], kv[kc * 16 + 2 * t + 9]);
                *(uint2*)(k16 + (fragBase + kc) * 64 + (gl + t) * 2) = u;
            }
        }
    }
}

// ===========================================================================
// Flash attention v6: pre-packed K/V fp16 images (zero per-tile cvts),
// fp16 m16n8k16, fixed-shift softmax, register-direct P (proven core).
// Epilogue writes out-proj B-frag image.
// ===========================================================================
#define ATT_SMEM_BYTES (64 * 132 * 4)

__global__ __launch_bounds__(256, 2)
void attn_f16_kernel(const float* __restrict__ qkv,
                     const uint32_t* __restrict__ Kimg,
                     const uint32_t* __restrict__ Vimg,
                     uint32_t* __restrict__ ao16)
{
    extern __shared__ char smc[];
    uint2* Kf = (uint2*)smc;          // 32 frags * 32 lanes (8KB)
    uint2* Vf = Kf + 1024;            // 8KB
    float* Ts = (float*)smc;          // epilogue reuse (64 x 132)

    const int tid  = threadIdx.x;
    const int wid  = tid >> 5;
    const int lane = tid & 31;
    const int g = lane >> 2;
    const int t = lane & 3;
    const int r0 = wid * 16;

    const int i0 = blockIdx.x * 128;
    const int h  = blockIdx.y;
    const int b  = blockIdx.z;
    const int bh = b * HEADS + h;

    const float* qb = qkv + ((size_t)b * O3 + (size_t)h * DHEAD) * NSEQ;

    // per-warp image bases
    const uint32_t* KimgW = Kimg + ((size_t)bh * 256 + wid) * 4 * 64 + lane * 2;
    const uint32_t* VimgW = Vimg + ((size_t)(bh * 8 + wid)) * 128 * 64 + lane * 2;

    // ---- Q A-fragments (fp16), from fp32 q (once per kernel)
    uint32_t qf[4][4];
    {
        const int col = i0 + r0 + g;
        #pragma unroll
        for (int kc = 0; kc < 4; kc++) {
            const float* q0 = qb + (size_t)(kc * 16 + 2 * t) * NSEQ + col;
            const float* q1 = q0 + NSEQ;
            qf[kc][0] = pack_h2(q0[0] * ATT_SCALE, q1[0] * ATT_SCALE);
            qf[kc][1] = pack_h2(q0[8] * ATT_SCALE, q1[8] * ATT_SCALE);
            qf[kc][2] = pack_h2(q0[(size_t)8 * NSEQ] * ATT_SCALE,
                                q1[(size_t)8 * NSEQ] * ATT_SCALE);
            qf[kc][3] = pack_h2(q0[(size_t)8 * NSEQ + 8] * ATT_SCALE,
                                q1[(size_t)8 * NSEQ + 8] * ATT_SCALE);
        }
    }

    // ---- preload K tile 0 frags (warp w: nt = j0/8 + w, kc 0..3)
    uint2 kimg[4];
    #pragma unroll
    for (int kc = 0; kc < 4; kc++)
        kimg[kc] = *(const uint2*)(KimgW + (size_t)kc * 64);

    float lp0 = 0.0f, lp1 = 0.0f;
    float o[8][4];
    #pragma unroll
    for (int dt = 0; dt < 8; dt++)
        #pragma unroll
        for (int r = 0; r < 4; r++) o[dt][r] = 0.0f;

    for (int j0 = 0; j0 < NSEQ; j0 += 64) {
        // ---- publish K frags (no cvts)
        #pragma unroll
        for (int kc = 0; kc < 4; kc++)
            Kf[(wid * 4 + kc) * 32 + lane] = kimg[kc];
        __syncthreads();

        // ---- issue V image loads (covered by S-MMA + softmax)
        uint2 vimg[4];
        #pragma unroll
        for (int kc = 0; kc < 4; kc++)
            vimg[kc] = *(const uint2*)(VimgW + (size_t)((j0 >> 4) + kc) * 64);

        // ---- S = Q K^T
        float s[8][4];
        #pragma unroll
        for (int nt = 0; nt < 8; nt++)
            #pragma unroll
            for (int r = 0; r < 4; r++) s[nt][r] = 0.0f;

        #pragma unroll
        for (int kc = 0; kc < 4; kc++)
            #pragma unroll
            for (int nt = 0; nt < 8; nt++) {
                uint2 kb2 = Kf[(nt * 4 + kc) * 32 + lane];
                mma_f16(s[nt], qf[kc], kb2.x, kb2.y);
            }

        // ---- fixed-shift softmax, register-resident P' = exp(s + 1)
        #pragma unroll
        for (int nt = 0; nt < 8; nt++) {
            s[nt][0] = __expf(s[nt][0] + 1.0f);
            s[nt][1] = __expf(s[nt][1] + 1.0f);
            s[nt][2] = __expf(s[nt][2] + 1.0f);
            s[nt][3] = __expf(s[nt][3] + 1.0f);
            lp0 += s[nt][0] + s[nt][1];
            lp1 += s[nt][2] + s[nt][3];
        }
        uint32_t pa[4][4];
        #pragma unroll
        for (int kc = 0; kc < 4; kc++) {
            pa[kc][0] = pack_h2(s[2 * kc][0],     s[2 * kc][1]);
            pa[kc][1] = pack_h2(s[2 * kc][2],     s[2 * kc][3]);
            pa[kc][2] = pack_h2(s[2 * kc + 1][0], s[2 * kc + 1][1]);
            pa[kc][3] = pack_h2(s[2 * kc + 1][2], s[2 * kc + 1][3]);
        }

        // ---- publish V frags (no cvts)
        #pragma unroll
        for (int kc = 0; kc < 4; kc++)
            Vf[(wid * 4 + kc) * 32 + lane] = vimg[kc];
        __syncthreads();

        // ---- prefetch next K tile (covered by PV)
        const int jn = (j0 + 64 < NSEQ) ? j0 + 64 : 0;
        #pragma unroll
        for (int kc = 0; kc < 4; kc++)
            kimg[kc] = *(const uint2*)(KimgW + ((size_t)(jn >> 3) * 4 + kc) * 64);

        // ---- O += P' V^T
        #pragma unroll
        for (int kc = 0; kc < 4; kc++)
            #pragma unroll
            for (int dt = 0; dt < 8; dt++) {
                uint2 vb2 = Vf[(dt * 4 + kc) * 32 + lane];
                mma_f16(o[dt], pa[kc], vb2.x, vb2.y);
            }
    }

    lp0 += __shfl_xor_sync(0xffffffffu, lp0, 1);
    lp0 += __shfl_xor_sync(0xffffffffu, lp0, 2);
    lp1 += __shfl_xor_sync(0xffffffffu, lp1, 1);
    lp1 += __shfl_xor_sync(0xffffffffu, lp1, 2);
    const float inv0 = 1.0f / lp0;
    const float inv1 = 1.0f / lp1;

    __syncthreads();

    #pragma unroll
    for (int dt = 0; dt < 8; dt++) {
        Ts[(dt * 8 + 2 * t)     * 132 + r0 + g]     = o[dt][0] * inv0;
        Ts[(dt * 8 + 2 * t + 1) * 132 + r0 + g]     = o[dt][1] * inv0;
        Ts[(dt * 8 + 2 * t)     * 132 + r0 + g + 8] = o[dt][2] * inv1;
        Ts[(dt * 8 + 2 * t + 1) * 132 + r0 + g + 8] = o[dt][3] * inv1;
    }
    __syncthreads();

    // ---- write out-proj B-frag image (proven round 15)
    for (int e = tid; e < 2048; e += 256) {
        const int ln  = e & 31;
        const int f   = e >> 5;
        const int kcL = f & 3;
        const int ntL = f >> 2;
        const int gg = ln >> 2, tt = ln & 3;
        const int i  = ntL * 8 + gg;
        const int d0 = kcL * 16 + 2 * tt;
        uint2 u;
        u.x = pack_h2(Ts[d0 * 132 + i],       Ts[(d0 + 1) * 132 + i]);
        u.y = pack_h2(Ts[(d0 + 8) * 132 + i], Ts[(d0 + 9) * 132 + i]);
        const size_t dst = ((size_t)(b * (NSEQ >> 3) + (i0 >> 3) + ntL) * (HDIM >> 4)
                            + (h * 4 + kcL)) * 64 + ln * 2;
        *(uint2*)(ao16 + dst) = u;
    }
}

// ---------------------------------------------------------------------------
extern "C" void kernel_launch(void* const* d_in, const int* in_sizes, int n_in,
                              void* d_out, int out_size)
{
    const float* x       = (const float*)d_in[0];
    const float* Wqkv    = (const float*)d_in[1];
    const float* q_scale = (const float*)d_in[2];
    const float* k_scale = (const float*)d_in[3];
    const float* Wout    = (const float*)d_in[4];
    const float* bout    = (const float*)d_in[5];
    float*       out     = (float*)d_out;

    float *qkv = nullptr;
    uint32_t *wq16 = nullptr, *wo16 = nullptr, *x16 = nullptr, *ao16 = nullptr;
    uint32_t *k16 = nullptr, *v16 = nullptr;
    cudaGetSymbolAddress((void**)&qkv,  g_qkv);
    cudaGetSymbolAddress((void**)&wq16, g_wqkv16);
    cudaGetSymbolAddress((void**)&wo16, g_wout16);
    cudaGetSymbolAddress((void**)&x16,  g_x16);
    cudaGetSymbolAddress((void**)&ao16, g_ao16);
    cudaGetSymbolAddress((void**)&k16,  g_k16);
    cudaGetSymbolAddress((void**)&v16,  g_v16);

    cudaFuncSetAttribute(f16_gemm_kernel,
                         cudaFuncAttributeMaxDynamicSharedMemorySize, GT_SMEM_BYTES);
    cudaFuncSetAttribute(attn_f16_kernel,
                         cudaFuncAttributeMaxDynamicSharedMemorySize, ATT_SMEM_BYTES);

    // 0) pre-pack weight/input fp16 fragment images
    pack_a_kernel<<<(O3 / 16) * (CIN / 16) * 32 / 256, 256>>>(Wqkv, wq16, O3, CIN);
    pack_a_kernel<<<(CIN / 16) * (HDIM / 16) * 32 / 256, 256>>>(Wout, wo16, CIN, HDIM);
    {
        dim3 gb((NSEQ / 8) * (CIN / 16) * 32 / 256, BATCH);
        pack_b_kernel<<<gb, 256>>>(x, x16, CIN, NSEQ);
    }

    // 1) QKV projection (fp16, pre-packed, K32 double-buffered, 2 CTA/SM)
    f16_gemm_kernel<<<dim3(NSEQ / 128, O3 / 128, BATCH), 256, GT_SMEM_BYTES>>>(
        wq16, x16, qkv, nullptr, O3, CIN, NSEQ);

    // 2) l2-normalize: q -> fp32 in place; k -> K B-frag fp16 image
    l2norm_kernel<<<dim3(NSEQ / 256, HEADS, BATCH * 2), 256>>>(
        qkv, q_scale, k_scale, k16);

    // 2b) pack V fp16 image
    pack_v_kernel<<<BATCH * HEADS * 8 * 128 * 32 / 256, 256>>>(qkv, v16);

    // 3) flash attention (pre-packed K/V images); epilogue emits ao16 image
    attn_f16_kernel<<<dim3(NSEQ / 128, HEADS, BATCH), 256, ATT_SMEM_BYTES>>>(
        qkv, k16, v16, ao16);

    // 4) output projection (fp16, pre-packed) + bias
    f16_gemm_kernel<<<dim3(NSEQ / 128, CIN / 128, BATCH), 256, GT_SMEM_BYTES>>>(
        wo16, ao16, out, bout, CIN, HDIM, NSEQ);
}